// round 14
// baseline (speedup 1.0000x reference)
#include <cuda_runtime.h>
#include <math.h>
#include <stdint.h>

#define NEDGE 320000
#define NUN   10000
#define NVN   10000
#define FIN   128

// ---------------- scratch (static device globals; no allocation) ------------
__device__ float g_pu[NUN * 256];
__device__ float g_pv[NVN * 256];
__device__ float g_att_u[NUN * 256];
__device__ float g_att_v[NVN * 256];
__device__ float g_agg_u[NUN * 256];   // UNNORMALIZED exp-weighted sums
__device__ float g_agg_v[NVN * 256];
__device__ float g_s_bwd[NUN];         // segment sums of exp
__device__ float g_s_fwd[NVN];
// CSR scratch
__device__ int g_cnt_u[NUN + 1];
__device__ int g_cnt_v[NVN + 1];
__device__ int g_ptr_u[NUN + 1];
__device__ int g_ptr_v[NVN + 1];
__device__ int g_eid_u[NEDGE];
__device__ int g_eid_v[NEDGE];

__device__ __forceinline__ float f2tf32(float f) {
    uint32_t r;
    asm("cvt.rna.tf32.f32 %0, %1;" : "=r"(r) : "f"(f));
    return __uint_as_float(r);
}
__device__ __forceinline__ void mma_tf32(float* d, const uint32_t* a,
                                         uint32_t b0, uint32_t b1) {
    asm volatile(
        "mma.sync.aligned.m16n8k8.row.col.f32.tf32.tf32.f32 "
        "{%0,%1,%2,%3}, {%4,%5,%6,%7}, {%8,%9}, {%0,%1,%2,%3};"
        : "+f"(d[0]), "+f"(d[1]), "+f"(d[2]), "+f"(d[3])
        : "r"(a[0]), "r"(a[1]), "r"(a[2]), "r"(a[3]), "r"(b0), "r"(b1));
}

// ---------------- CSR build --------------------------------------------------
__global__ void zerocnt_kernel() {
    int i = blockIdx.x * blockDim.x + threadIdx.x;
    if (i <= NUN) g_cnt_u[i] = 0;
    if (i <= NVN) g_cnt_v[i] = 0;
}
__global__ void hist_kernel(const int* __restrict__ src, const int* __restrict__ dst) {
    int e = blockIdx.x * 256 + threadIdx.x;
    if (e < NEDGE) {
        atomicAdd(&g_cnt_u[src[e]], 1);
        atomicAdd(&g_cnt_v[dst[e]], 1);
    }
}
// exclusive scan over 10000 counters; writes ptr[] and resets cnt[] = ptr[]
__global__ void scan_kernel() {
    int* cnt = blockIdx.x ? g_cnt_v : g_cnt_u;
    int* ptr = blockIdx.x ? g_ptr_v : g_ptr_u;
    const int N = 10000;
    __shared__ int sh[1024];
    __shared__ int carry;
    if (threadIdx.x == 0) carry = 0;
    __syncthreads();
    for (int base = 0; base < N; base += 1024) {
        int i = base + threadIdx.x;
        int v = (i < N) ? cnt[i] : 0;
        sh[threadIdx.x] = v;
        __syncthreads();
        for (int off = 1; off < 1024; off <<= 1) {
            int t = (threadIdx.x >= off) ? sh[threadIdx.x - off] : 0;
            __syncthreads();
            sh[threadIdx.x] += t;
            __syncthreads();
        }
        int excl = carry + sh[threadIdx.x] - v;
        if (i < N) { ptr[i] = excl; cnt[i] = excl; }
        __syncthreads();
        if (threadIdx.x == 1023) carry += sh[1023];
        __syncthreads();
    }
    if (threadIdx.x == 0) ptr[N] = carry;
}
__global__ void scatter_kernel(const int* __restrict__ src, const int* __restrict__ dst) {
    int e = blockIdx.x * 256 + threadIdx.x;
    if (e < NEDGE) {
        int p1 = atomicAdd(&g_cnt_u[src[e]], 1);
        g_eid_u[p1] = e;
        int p2 = atomicAdd(&g_cnt_v[dst[e]], 1);
        g_eid_v[p2] = e;
    }
}

// ---------------- gather-side aggregation: one warp per node ----------------
// agg_u[u] = sum_e exp(<[v[dst],e], att_u[u]>) * [v[dst], e];  s_bwd[u] = sum exp
__global__ void agg_u_kernel(const float* __restrict__ e_feat,
                             const float* __restrict__ v_feat,
                             const int* __restrict__ dst) {
    int u = blockIdx.x * 8 + (threadIdx.x >> 5);
    if (u >= NUN) return;
    int lane = threadIdx.x & 31;
    int c = lane * 4;
    float4 au0 = *(const float4*)&g_att_u[(size_t)u * 256 + c];
    float4 au1 = *(const float4*)&g_att_u[(size_t)u * 256 + 128 + c];
    float4 a0 = make_float4(0.f, 0.f, 0.f, 0.f);
    float4 a1 = make_float4(0.f, 0.f, 0.f, 0.f);
    float ssum = 0.f;
    int beg = g_ptr_u[u], end = g_ptr_u[u + 1];
    for (int k = beg; k < end; k++) {
        int e = g_eid_u[k];
        int d = dst[e];
        float4 vv = *(const float4*)&v_feat[(size_t)d * FIN + c];
        float4 ev = *(const float4*)&e_feat[(size_t)e * FIN + c];
        float p = vv.x * au0.x + vv.y * au0.y + vv.z * au0.z + vv.w * au0.w
                + ev.x * au1.x + ev.y * au1.y + ev.z * au1.z + ev.w * au1.w;
#pragma unroll
        for (int o = 16; o; o >>= 1) p += __shfl_xor_sync(0xFFFFFFFFu, p, o);
        float wb = __expf(p);
        a0.x += wb * vv.x; a0.y += wb * vv.y; a0.z += wb * vv.z; a0.w += wb * vv.w;
        a1.x += wb * ev.x; a1.y += wb * ev.y; a1.z += wb * ev.z; a1.w += wb * ev.w;
        ssum += wb;
    }
    *(float4*)&g_agg_u[(size_t)u * 256 + c]       = a0;
    *(float4*)&g_agg_u[(size_t)u * 256 + 128 + c] = a1;
    if (lane == 0) g_s_bwd[u] = ssum;
}

__global__ void agg_v_kernel(const float* __restrict__ e_feat,
                             const float* __restrict__ u_feat,
                             const int* __restrict__ src) {
    int v = blockIdx.x * 8 + (threadIdx.x >> 5);
    if (v >= NVN) return;
    int lane = threadIdx.x & 31;
    int c = lane * 4;
    float4 av0 = *(const float4*)&g_att_v[(size_t)v * 256 + c];
    float4 av1 = *(const float4*)&g_att_v[(size_t)v * 256 + 128 + c];
    float4 a0 = make_float4(0.f, 0.f, 0.f, 0.f);
    float4 a1 = make_float4(0.f, 0.f, 0.f, 0.f);
    float ssum = 0.f;
    int beg = g_ptr_v[v], end = g_ptr_v[v + 1];
    for (int k = beg; k < end; k++) {
        int e = g_eid_v[k];
        int s = src[e];
        float4 uv = *(const float4*)&u_feat[(size_t)s * FIN + c];
        float4 ev = *(const float4*)&e_feat[(size_t)e * FIN + c];
        float p = uv.x * av0.x + uv.y * av0.y + uv.z * av0.z + uv.w * av0.w
                + ev.x * av1.x + ev.y * av1.y + ev.z * av1.z + ev.w * av1.w;
#pragma unroll
        for (int o = 16; o; o >>= 1) p += __shfl_xor_sync(0xFFFFFFFFu, p, o);
        float wf = __expf(p);
        a0.x += wf * uv.x; a0.y += wf * uv.y; a0.z += wf * uv.z; a0.w += wf * uv.w;
        a1.x += wf * ev.x; a1.y += wf * ev.y; a1.z += wf * ev.z; a1.w += wf * ev.w;
        ssum += wf;
    }
    *(float4*)&g_agg_v[(size_t)v * 256 + c]       = a0;
    *(float4*)&g_agg_v[(size_t)v * 256 + 128 + c] = a1;
    if (lane == 0) g_s_fwd[v] = ssum;
}

// =====================  tf32 tensor-core GEMM (R3/R5-proven body)  ==========
// MODE 0: plain   MODE 2: relu
// MODE 3: relu(.. + g_pu[src[r]] + g_pv[dst[r]])
// MODE 4: relu, A row r scaled by 1/rowScale[r]
template <int BN, int KTOT, int MODE>
__launch_bounds__(128)
__global__ void tf32gemm(const float* __restrict__ A,
                         const float* __restrict__ W,
                         const float* __restrict__ bias,
                         float* __restrict__ C, int ldc, int col_off, int M,
                         const int* __restrict__ src, const int* __restrict__ dst,
                         const float* __restrict__ rowScale) {
    constexpr int KC = 32;
    constexpr int WN = BN / 4;
    constexpr int NT = WN / 8;
    constexpr int ASTR = KC + 4;          // 36 ≡ 4 (mod 32)
    constexpr int BSTR = BN + 8;          // ≡ 8 (mod 32)
    __shared__ float As[64 * ASTR];
    __shared__ float Bs[KC * BSTR];

    const int t    = threadIdx.x;
    const int warp = t >> 5;
    const int lane = t & 31;
    const int qr   = lane >> 2;
    const int qc   = lane & 3;
    const int row0 = blockIdx.x * 64;

    float acc[4][NT][4];
#pragma unroll
    for (int i = 0; i < 4; i++)
#pragma unroll
        for (int j = 0; j < NT; j++)
#pragma unroll
            for (int q = 0; q < 4; q++) acc[i][j][q] = 0.f;

    for (int k0 = 0; k0 < KTOT; k0 += KC) {
#pragma unroll
        for (int p = 0; p < 4; p++) {
            int slot = t + p * 128;
            int r = slot >> 3, c = slot & 7;
            float4 v = make_float4(0.f, 0.f, 0.f, 0.f);
            int gr = row0 + r;
            if (gr < M) {
                v = *(const float4*)&A[(size_t)gr * KTOT + k0 + c * 4];
                if (MODE == 4) {
                    float sden = rowScale[gr];
                    float rs = sden > 0.f ? __fdividef(1.f, sden) : 0.f;
                    v.x *= rs; v.y *= rs; v.z *= rs; v.w *= rs;
                }
            }
            float* s = &As[r * ASTR + c * 4];
            s[0] = f2tf32(v.x); s[1] = f2tf32(v.y);
            s[2] = f2tf32(v.z); s[3] = f2tf32(v.w);
        }
#pragma unroll
        for (int p = 0; p < KC * BN / 512; p++) {
            int slot = t + p * 128;
            int kr = slot / (BN / 4);
            int c  = slot % (BN / 4);
            float4 v = *(const float4*)&W[(size_t)(k0 + kr) * BN + c * 4];
            float* s = &Bs[kr * BSTR + c * 4];
            s[0] = f2tf32(v.x); s[1] = f2tf32(v.y);
            s[2] = f2tf32(v.z); s[3] = f2tf32(v.w);
        }
        __syncthreads();
#pragma unroll
        for (int kk = 0; kk < KC; kk += 8) {
            uint32_t a[4][4];
#pragma unroll
            for (int i = 0; i < 4; i++) {
                const float* base = &As[(16 * i + qr) * ASTR + kk + qc];
                a[i][0] = __float_as_uint(base[0]);
                a[i][1] = __float_as_uint(base[8 * ASTR]);
                a[i][2] = __float_as_uint(base[4]);
                a[i][3] = __float_as_uint(base[8 * ASTR + 4]);
            }
#pragma unroll
            for (int j = 0; j < NT; j++) {
                int n = warp * WN + j * 8 + qr;
                uint32_t b0 = __float_as_uint(Bs[(kk + qc) * BSTR + n]);
                uint32_t b1 = __float_as_uint(Bs[(kk + 4 + qc) * BSTR + n]);
#pragma unroll
                for (int i = 0; i < 4; i++) mma_tf32(acc[i][j], a[i], b0, b1);
            }
        }
        __syncthreads();
    }

#pragma unroll
    for (int i = 0; i < 4; i++) {
#pragma unroll
        for (int h = 0; h < 2; h++) {
            int gr = row0 + 16 * i + qr + 8 * h;
            if (gr >= M) continue;
            int s_ = 0, d_ = 0;
            if (MODE == 3) { s_ = src[gr]; d_ = dst[gr]; }
#pragma unroll
            for (int j = 0; j < NT; j++) {
                int col = warp * WN + j * 8 + 2 * qc;
                float x0 = acc[i][j][2 * h]     + bias[col];
                float x1 = acc[i][j][2 * h + 1] + bias[col + 1];
                if (MODE == 3) {
                    const float* pu = &g_pu[0] + (size_t)s_ * 256 + col;
                    const float* pv = &g_pv[0] + (size_t)d_ * 256 + col;
                    x0 += pu[0] + pv[0];
                    x1 += pu[1] + pv[1];
                }
                if (MODE >= 2) { x0 = fmaxf(x0, 0.f); x1 = fmaxf(x1, 0.f); }
                *(float2*)&C[(size_t)gr * ldc + col_off + col] = make_float2(x0, x1);
            }
        }
    }
}

// ---------------- launch: 3-stream CUDA-graph DAG ----------------------------
extern "C" void kernel_launch(void* const* d_in, const int* in_sizes, int n_in,
                              void* d_out, int out_size) {
    const float* e_feat = (const float*)d_in[0];
    const float* u_feat = (const float*)d_in[1];
    const float* v_feat = (const float*)d_in[2];
    const int*   src    = (const int*)d_in[3];
    const int*   dst    = (const int*)d_in[4];
    const float* We  = (const float*)d_in[5];  const float* be  = (const float*)d_in[6];
    const float* Wu  = (const float*)d_in[7];  const float* bu  = (const float*)d_in[8];
    const float* Wv  = (const float*)d_in[9];  const float* bv  = (const float*)d_in[10];
    const float* Wau = (const float*)d_in[11]; const float* bau = (const float*)d_in[12];
    const float* Wav = (const float*)d_in[13]; const float* bav = (const float*)d_in[14];
    const float* Wnu = (const float*)d_in[15]; const float* bnu = (const float*)d_in[16];
    const float* Wnv = (const float*)d_in[17]; const float* bnv = (const float*)d_in[18];
    const float* Vu  = (const float*)d_in[19]; const float* bVu = (const float*)d_in[20];
    const float* Vv  = (const float*)d_in[21]; const float* bVv = (const float*)d_in[22];

    float* out    = (float*)d_out;
    float* out_he = out;
    float* out_hu = out + (size_t)NEDGE * 256;
    float* out_hv = out_hu + (size_t)NUN * 256;

    float *pu, *pv, *au, *av, *aggu, *aggv, *sb, *sf;
    cudaGetSymbolAddress((void**)&pu,   g_pu);
    cudaGetSymbolAddress((void**)&pv,   g_pv);
    cudaGetSymbolAddress((void**)&au,   g_att_u);
    cudaGetSymbolAddress((void**)&av,   g_att_v);
    cudaGetSymbolAddress((void**)&aggu, g_agg_u);
    cudaGetSymbolAddress((void**)&aggv, g_agg_v);
    cudaGetSymbolAddress((void**)&sb,   g_s_bwd);
    cudaGetSymbolAddress((void**)&sf,   g_s_fwd);

    static cudaStream_t s1, s2, s3;
    static cudaEvent_t evRoot, evPu, evPv, evAttV, evAgg, evSkip, evHv;
    static bool once = false;
    if (!once) {
        cudaStreamCreateWithFlags(&s1, cudaStreamNonBlocking);
        cudaStreamCreateWithFlags(&s2, cudaStreamNonBlocking);
        cudaStreamCreateWithFlags(&s3, cudaStreamNonBlocking);
        cudaEventCreateWithFlags(&evRoot, cudaEventDisableTiming);
        cudaEventCreateWithFlags(&evPu,   cudaEventDisableTiming);
        cudaEventCreateWithFlags(&evPv,   cudaEventDisableTiming);
        cudaEventCreateWithFlags(&evAttV, cudaEventDisableTiming);
        cudaEventCreateWithFlags(&evAgg,  cudaEventDisableTiming);
        cudaEventCreateWithFlags(&evSkip, cudaEventDisableTiming);
        cudaEventCreateWithFlags(&evHv,   cudaEventDisableTiming);
        once = true;
    }

    const int MB = (NUN + 63) / 64;   // 157

    cudaEventRecord(evRoot, 0);

    // (1) s1: pu projection
    cudaStreamWaitEvent(s1, evRoot, 0);
    tf32gemm<256, 128, 0><<<MB, 128, 0, s1>>>(u_feat, Wu, bu, pu, 256, 0, NUN,
                                              nullptr, nullptr, nullptr);
    cudaEventRecord(evPu, s1);

    // (2) s3: pv projection
    cudaStreamWaitEvent(s3, evRoot, 0);
    tf32gemm<256, 128, 0><<<MB, 128, 0, s3>>>(v_feat, Wv, bv, pv, 256, 0, NVN,
                                              nullptr, nullptr, nullptr);
    cudaEventRecord(evPv, s3);

    // (3) s1: att_v projection
    tf32gemm<256, 128, 0><<<MB, 128, 0, s1>>>(v_feat, Wav, bav, av, 256, 0, NVN,
                                              nullptr, nullptr, nullptr);
    cudaEventRecord(evAttV, s1);

    // (4) s2: att_u projection
    cudaStreamWaitEvent(s2, evRoot, 0);
    tf32gemm<256, 128, 0><<<MB, 128, 0, s2>>>(u_feat, Wau, bau, au, 256, 0, NUN,
                                              nullptr, nullptr, nullptr);

    // (5) s2: CSR build begins
    zerocnt_kernel<<<(NUN + 256) / 256, 256, 0, s2>>>();

    // (6) main: he (waits pu AND pv) — ncu slot target
    cudaStreamWaitEvent(0, evPu, 0);
    cudaStreamWaitEvent(0, evPv, 0);
    tf32gemm<256, 128, 3><<<NEDGE / 64, 128>>>(e_feat, We, be, out_he, 256, 0,
                                               NEDGE, src, dst, nullptr);

    // s2: rest of CSR build + gather aggregation + head_v
    hist_kernel<<<(NEDGE + 255) / 256, 256, 0, s2>>>(src, dst);
    scan_kernel<<<2, 1024, 0, s2>>>();
    scatter_kernel<<<(NEDGE + 255) / 256, 256, 0, s2>>>(src, dst);
    agg_u_kernel<<<(NUN + 7) / 8, 256, 0, s2>>>(e_feat, v_feat, dst);
    cudaStreamWaitEvent(s2, evAttV, 0);
    agg_v_kernel<<<(NVN + 7) / 8, 256, 0, s2>>>(e_feat, u_feat, src);
    cudaEventRecord(evAgg, s2);
    tf32gemm<128, 256, 4><<<MB, 128, 0, s2>>>(aggv, Wnv, bnv, out_hv, 256, 128, NVN,
                                              nullptr, nullptr, sf);
    cudaEventRecord(evHv, s2);

    // s3: skip-connection halves of hu / hv
    tf32gemm<128, 128, 0><<<MB, 128, 0, s3>>>(u_feat, Vu, bVu, out_hu, 256, 0, NUN,
                                              nullptr, nullptr, nullptr);
    tf32gemm<128, 128, 0><<<MB, 128, 0, s3>>>(v_feat, Vv, bVv, out_hv, 256, 0, NVN,
                                              nullptr, nullptr, nullptr);
    cudaEventRecord(evSkip, s3);

    // main: head_u after aggregation; join all branches
    cudaStreamWaitEvent(0, evAgg, 0);
    tf32gemm<128, 256, 4><<<MB, 128>>>(aggu, Wnu, bnu, out_hu, 256, 128, NUN,
                                       nullptr, nullptr, sb);
    cudaStreamWaitEvent(0, evHv, 0);
    cudaStreamWaitEvent(0, evSkip, 0);
}

// round 16
// speedup vs baseline: 1.0826x; 1.0826x over previous
#include <cuda_runtime.h>
#include <math.h>
#include <stdint.h>

#define NEDGE 320000
#define NUN   10000
#define NVN   10000
#define FIN   128

// ---------------- scratch (static device globals; no allocation) ------------
__device__ float g_pu[NUN * 256];
__device__ float g_pv[NVN * 256];
__device__ float g_att_u[NUN * 256];
__device__ float g_att_v[NVN * 256];
__device__ float g_agg_u[NUN * 256];   // UNNORMALIZED exp-weighted sums
__device__ float g_agg_v[NVN * 256];
__device__ float g_s_bwd[NUN];         // segment sums of exp
__device__ float g_s_fwd[NVN];

__device__ __forceinline__ float f2tf32(float f) {
    uint32_t r;
    asm("cvt.rna.tf32.f32 %0, %1;" : "=r"(r) : "f"(f));
    return __uint_as_float(r);
}
__device__ __forceinline__ void mma_tf32(float* d, const uint32_t* a,
                                         uint32_t b0, uint32_t b1) {
    asm volatile(
        "mma.sync.aligned.m16n8k8.row.col.f32.tf32.tf32.f32 "
        "{%0,%1,%2,%3}, {%4,%5,%6,%7}, {%8,%9}, {%0,%1,%2,%3};"
        : "+f"(d[0]), "+f"(d[1]), "+f"(d[2]), "+f"(d[3])
        : "r"(a[0]), "r"(a[1]), "r"(a[2]), "r"(a[3]), "r"(b0), "r"(b1));
}
__device__ __forceinline__ void red4(float* p, float4 v) {
    asm volatile("red.global.add.v4.f32 [%0], {%1,%2,%3,%4};"
                 :: "l"(p), "f"(v.x), "f"(v.y), "f"(v.z), "f"(v.w) : "memory");
}

// ---------------- init ------------------------------------------------------
__global__ void init_kernel() {
    int i = blockIdx.x * blockDim.x + threadIdx.x;
    if (i < NUN * 256) g_agg_u[i] = 0.f;
    if (i < NVN * 256) g_agg_v[i] = 0.f;
    if (i < NUN) g_s_bwd[i] = 0.f;
    if (i < NVN) g_s_fwd[i] = 0.f;
}

// ============  GEMM body shared by single and dual variants  =================
// BM=64, 128 threads, warp tile 64 x (BN/4), mma.m16n8k8.tf32, KC=32,
// cvt once at smem store.
template <int BN, int KTOT, int MODE>
__device__ __forceinline__ void gemm_body(
        const float* __restrict__ A, const float* __restrict__ W,
        const float* __restrict__ bias, float* __restrict__ C,
        int ldc, int col_off, int M, int row0,
        const int* __restrict__ src, const int* __restrict__ dst,
        const float* __restrict__ rowScale) {
    constexpr int KC = 32;
    constexpr int WN = BN / 4;
    constexpr int NT = WN / 8;
    constexpr int ASTR = KC + 4;          // 36 ≡ 4 (mod 32)
    constexpr int BSTR = BN + 8;          // ≡ 8 (mod 32)
    __shared__ float As[64 * ASTR];
    __shared__ float Bs[KC * BSTR];

    const int t    = threadIdx.x;
    const int warp = t >> 5;
    const int lane = t & 31;
    const int qr   = lane >> 2;
    const int qc   = lane & 3;

    float acc[4][NT][4];
#pragma unroll
    for (int i = 0; i < 4; i++)
#pragma unroll
        for (int j = 0; j < NT; j++)
#pragma unroll
            for (int q = 0; q < 4; q++) acc[i][j][q] = 0.f;

    for (int k0 = 0; k0 < KTOT; k0 += KC) {
#pragma unroll
        for (int p = 0; p < 4; p++) {
            int slot = t + p * 128;
            int r = slot >> 3, c = slot & 7;
            float4 v = make_float4(0.f, 0.f, 0.f, 0.f);
            int gr = row0 + r;
            if (gr < M) {
                v = *(const float4*)&A[(size_t)gr * KTOT + k0 + c * 4];
                if (MODE == 4) {
                    float sden = rowScale[gr];
                    float rs = sden > 0.f ? __fdividef(1.f, sden) : 0.f;
                    v.x *= rs; v.y *= rs; v.z *= rs; v.w *= rs;
                }
            }
            float* s = &As[r * ASTR + c * 4];
            s[0] = f2tf32(v.x); s[1] = f2tf32(v.y);
            s[2] = f2tf32(v.z); s[3] = f2tf32(v.w);
        }
#pragma unroll
        for (int p = 0; p < KC * BN / 512; p++) {
            int slot = t + p * 128;
            int kr = slot / (BN / 4);
            int c  = slot % (BN / 4);
            float4 v = *(const float4*)&W[(size_t)(k0 + kr) * BN + c * 4];
            float* s = &Bs[kr * BSTR + c * 4];
            s[0] = f2tf32(v.x); s[1] = f2tf32(v.y);
            s[2] = f2tf32(v.z); s[3] = f2tf32(v.w);
        }
        __syncthreads();
#pragma unroll
        for (int kk = 0; kk < KC; kk += 8) {
            uint32_t a[4][4];
#pragma unroll
            for (int i = 0; i < 4; i++) {
                const float* base = &As[(16 * i + qr) * ASTR + kk + qc];
                a[i][0] = __float_as_uint(base[0]);
                a[i][1] = __float_as_uint(base[8 * ASTR]);
                a[i][2] = __float_as_uint(base[4]);
                a[i][3] = __float_as_uint(base[8 * ASTR + 4]);
            }
#pragma unroll
            for (int j = 0; j < NT; j++) {
                int n = warp * WN + j * 8 + qr;
                uint32_t b0 = __float_as_uint(Bs[(kk + qc) * BSTR + n]);
                uint32_t b1 = __float_as_uint(Bs[(kk + 4 + qc) * BSTR + n]);
#pragma unroll
                for (int i = 0; i < 4; i++) mma_tf32(acc[i][j], a[i], b0, b1);
            }
        }
        __syncthreads();
    }

#pragma unroll
    for (int i = 0; i < 4; i++) {
#pragma unroll
        for (int h = 0; h < 2; h++) {
            int gr = row0 + 16 * i + qr + 8 * h;
            if (gr >= M) continue;
            int s_ = 0, d_ = 0;
            if (MODE == 3) { s_ = src[gr]; d_ = dst[gr]; }
#pragma unroll
            for (int j = 0; j < NT; j++) {
                int col = warp * WN + j * 8 + 2 * qc;
                float x0 = acc[i][j][2 * h]     + bias[col];
                float x1 = acc[i][j][2 * h + 1] + bias[col + 1];
                if (MODE == 3) {
                    const float* pu = &g_pu[0] + (size_t)s_ * 256 + col;
                    const float* pv = &g_pv[0] + (size_t)d_ * 256 + col;
                    x0 += pu[0] + pv[0];
                    x1 += pu[1] + pv[1];
                }
                if (MODE >= 2) { x0 = fmaxf(x0, 0.f); x1 = fmaxf(x1, 0.f); }
                *(float2*)&C[(size_t)gr * ldc + col_off + col] = make_float2(x0, x1);
            }
        }
    }
}

// single-operand version (used for he, MODE 3)
template <int BN, int KTOT, int MODE>
__launch_bounds__(128)
__global__ void tf32gemm(const float* __restrict__ A,
                         const float* __restrict__ W,
                         const float* __restrict__ bias,
                         float* __restrict__ C, int ldc, int col_off, int M,
                         const int* __restrict__ src, const int* __restrict__ dst,
                         const float* __restrict__ rowScale) {
    gemm_body<BN, KTOT, MODE>(A, W, bias, C, ldc, col_off, M,
                              blockIdx.x * 64, src, dst, rowScale);
}

// dual-operand version: blockIdx.y selects operand set (node-table GEMM pairs)
template <int BN, int KTOT, int MODE>
__launch_bounds__(128)
__global__ void tf32gemm_dual(const float* __restrict__ A0, const float* __restrict__ W0,
                              const float* __restrict__ b0, float* __restrict__ C0,
                              const float* __restrict__ rs0,
                              const float* __restrict__ A1, const float* __restrict__ W1,
                              const float* __restrict__ b1, float* __restrict__ C1,
                              const float* __restrict__ rs1,
                              int ldc, int col_off, int M) {
    if (blockIdx.y == 0)
        gemm_body<BN, KTOT, MODE>(A0, W0, b0, C0, ldc, col_off, M,
                                  blockIdx.x * 64, nullptr, nullptr, rs0);
    else
        gemm_body<BN, KTOT, MODE>(A1, W1, b1, C1, ldc, col_off, M,
                                  blockIdx.x * 64, nullptr, nullptr, rs1);
}

// ===== fused edge pass: logit -> exp (no max shift; fp32-safe) -> scatter ====
__global__ void edge_kernel(const float* __restrict__ e_feat,
                            const float* __restrict__ u_feat,
                            const float* __restrict__ v_feat,
                            const int* __restrict__ src,
                            const int* __restrict__ dst) {
    int e = blockIdx.x * 8 + (threadIdx.x >> 5);
    int lane = threadIdx.x & 31;
    int c = lane * 4;
    int s = src[e], d = dst[e];
    float4 ev = *(const float4*)&e_feat[(size_t)e * FIN + c];
    float4 uv = *(const float4*)&u_feat[(size_t)s * FIN + c];
    float4 vv = *(const float4*)&v_feat[(size_t)d * FIN + c];
    float4 au0 = *(const float4*)&g_att_u[(size_t)s * 256 + c];
    float4 au1 = *(const float4*)&g_att_u[(size_t)s * 256 + 128 + c];
    float4 av0 = *(const float4*)&g_att_v[(size_t)d * 256 + c];
    float4 av1 = *(const float4*)&g_att_v[(size_t)d * 256 + 128 + c];
    float sb = vv.x * au0.x + vv.y * au0.y + vv.z * au0.z + vv.w * au0.w
             + ev.x * au1.x + ev.y * au1.y + ev.z * au1.z + ev.w * au1.w;
    float sf = uv.x * av0.x + uv.y * av0.y + uv.z * av0.z + uv.w * av0.w
             + ev.x * av1.x + ev.y * av1.y + ev.z * av1.z + ev.w * av1.w;
#pragma unroll
    for (int o = 16; o; o >>= 1) {
        sb += __shfl_xor_sync(0xFFFFFFFFu, sb, o);
        sf += __shfl_xor_sync(0xFFFFFFFFu, sf, o);
    }
    float wb = __expf(sb);
    float wf = __expf(sf);
    float* agu = g_agg_u + (size_t)s * 256;
    float* agv = g_agg_v + (size_t)d * 256;
    red4(&agu[c],       make_float4(wb * vv.x, wb * vv.y, wb * vv.z, wb * vv.w));
    red4(&agu[c + 128], make_float4(wb * ev.x, wb * ev.y, wb * ev.z, wb * ev.w));
    red4(&agv[c],       make_float4(wf * uv.x, wf * uv.y, wf * uv.z, wf * uv.w));
    red4(&agv[c + 128], make_float4(wf * ev.x, wf * ev.y, wf * ev.z, wf * ev.w));
    if (lane == 0) {
        atomicAdd(&g_s_bwd[s], wb);
        atomicAdd(&g_s_fwd[d], wf);
    }
}

// ---------------- launch: 3-stream CUDA-graph DAG ----------------------------
extern "C" void kernel_launch(void* const* d_in, const int* in_sizes, int n_in,
                              void* d_out, int out_size) {
    const float* e_feat = (const float*)d_in[0];
    const float* u_feat = (const float*)d_in[1];
    const float* v_feat = (const float*)d_in[2];
    const int*   src    = (const int*)d_in[3];
    const int*   dst    = (const int*)d_in[4];
    const float* We  = (const float*)d_in[5];  const float* be  = (const float*)d_in[6];
    const float* Wu  = (const float*)d_in[7];  const float* bu  = (const float*)d_in[8];
    const float* Wv  = (const float*)d_in[9];  const float* bv  = (const float*)d_in[10];
    const float* Wau = (const float*)d_in[11]; const float* bau = (const float*)d_in[12];
    const float* Wav = (const float*)d_in[13]; const float* bav = (const float*)d_in[14];
    const float* Wnu = (const float*)d_in[15]; const float* bnu = (const float*)d_in[16];
    const float* Wnv = (const float*)d_in[17]; const float* bnv = (const float*)d_in[18];
    const float* Vu  = (const float*)d_in[19]; const float* bVu = (const float*)d_in[20];
    const float* Vv  = (const float*)d_in[21]; const float* bVv = (const float*)d_in[22];

    float* out    = (float*)d_out;
    float* out_he = out;
    float* out_hu = out + (size_t)NEDGE * 256;
    float* out_hv = out_hu + (size_t)NUN * 256;

    float *pu, *pv, *au, *av, *aggu, *aggv, *sb, *sf;
    cudaGetSymbolAddress((void**)&pu,   g_pu);
    cudaGetSymbolAddress((void**)&pv,   g_pv);
    cudaGetSymbolAddress((void**)&au,   g_att_u);
    cudaGetSymbolAddress((void**)&av,   g_att_v);
    cudaGetSymbolAddress((void**)&aggu, g_agg_u);
    cudaGetSymbolAddress((void**)&aggv, g_agg_v);
    cudaGetSymbolAddress((void**)&sb,   g_s_bwd);
    cudaGetSymbolAddress((void**)&sf,   g_s_fwd);

    static cudaStream_t s1, s2, s3;
    static cudaEvent_t evRoot, evInit, evPP, evAtt, evAgg, evHeads, evSkip;
    static bool once = false;
    if (!once) {
        cudaStreamCreateWithFlags(&s1, cudaStreamNonBlocking);
        cudaStreamCreateWithFlags(&s2, cudaStreamNonBlocking);
        cudaStreamCreateWithFlags(&s3, cudaStreamNonBlocking);
        cudaEventCreateWithFlags(&evRoot,  cudaEventDisableTiming);
        cudaEventCreateWithFlags(&evInit,  cudaEventDisableTiming);
        cudaEventCreateWithFlags(&evPP,    cudaEventDisableTiming);
        cudaEventCreateWithFlags(&evAtt,   cudaEventDisableTiming);
        cudaEventCreateWithFlags(&evAgg,   cudaEventDisableTiming);
        cudaEventCreateWithFlags(&evHeads, cudaEventDisableTiming);
        cudaEventCreateWithFlags(&evSkip,  cudaEventDisableTiming);
        once = true;
    }

    const int MB = (NUN + 63) / 64;   // 157

    cudaEventRecord(evRoot, 0);

    // main: init scratch (edge scatter targets)
    init_kernel<<<(NUN * 256 + 255) / 256, 256>>>();
    cudaEventRecord(evInit, 0);

    // s1: pu + pv in one dual launch (feeds he epilogue)
    cudaStreamWaitEvent(s1, evRoot, 0);
    tf32gemm_dual<256, 128, 0><<<dim3(MB, 2), 128, 0, s1>>>(
        u_feat, Wu, bu, pu, nullptr,
        v_feat, Wv, bv, pv, nullptr, 256, 0, NUN);
    cudaEventRecord(evPP, s1);

    // s2: att_u + att_v dual, then edge pass, then both heads dual
    cudaStreamWaitEvent(s2, evRoot, 0);
    tf32gemm_dual<256, 128, 0><<<dim3(MB, 2), 128, 0, s2>>>(
        u_feat, Wau, bau, au, nullptr,
        v_feat, Wav, bav, av, nullptr, 256, 0, NUN);
    cudaStreamWaitEvent(s2, evInit, 0);
    edge_kernel<<<NEDGE / 8, 256, 0, s2>>>(e_feat, u_feat, v_feat, src, dst);
    cudaEventRecord(evAgg, s2);
    tf32gemm_dual<128, 256, 4><<<dim3(MB, 2), 128, 0, s2>>>(
        aggu, Wnu, bnu, out_hu, sb,
        aggv, Wnv, bnv, out_hv, sf, 256, 128, NUN);
    cudaEventRecord(evHeads, s2);

    // s3: skip halves of hu / hv in one dual launch
    cudaStreamWaitEvent(s3, evRoot, 0);
    tf32gemm_dual<128, 128, 0><<<dim3(MB, 2), 128, 0, s3>>>(
        u_feat, Vu, bVu, out_hu, nullptr,
        v_feat, Vv, bVv, out_hv, nullptr, 256, 0, NUN);
    cudaEventRecord(evSkip, s3);

    // main: he (waits pu+pv), concurrent with the edge chain on s2
    cudaStreamWaitEvent(0, evPP, 0);
    tf32gemm<256, 128, 3><<<NEDGE / 64, 128>>>(e_feat, We, be, out_he, 256, 0,
                                               NEDGE, src, dst, nullptr);

    // join all branches on main
    cudaStreamWaitEvent(0, evHeads, 0);
    cudaStreamWaitEvent(0, evSkip, 0);
}